// round 15
// baseline (speedup 1.0000x reference)
#include <cuda_runtime.h>
#include <cuda_bf16.h>
#include <cstdint>

// MaxUnpool2D — final form (round-12 shape, last untested store policy __stcg).
// Scatter-shaped gather: one thread per pooled float4 group; 2 coalesced 16B
// loads + 4 coalesced 16B stores covering the cell's private 2x2 output
// window. Argmax indices are unique per pooled cell -> every output element
// written exactly once; no atomics, no zero-init pass.
//
// Session evidence: six structurally different designs (gather, scatter STG,
// far-pair MLP=2, persistent single-wave, write-through, TMA 32KB bulk)
// all converge at kernel 28.5-30us with no pipe >64% — a mixed read/write
// DRAM-efficiency floor. Demand traffic is provably minimal (64MB compulsory
// read + 128MB compulsory write). DRAM write order = L2 eviction order,
// which is why store-path restructuring is invariant.
//
// x:    [B=8, H=128, W=128, C=64] float32
// mask: [B, H, W, C] int32 (flat idx into [HOUT*WOUT*C] per batch)
// out:  [B, 256, 256, C] float32

static constexpr int Bc   = 8;
static constexpr int Hc   = 128;
static constexpr int Wc   = 128;
static constexpr int Cc   = 64;
static constexpr int HOUT = 256;
static constexpr int WOUT = 256;
static constexpr int C4   = Cc / 4;             // 16
static constexpr int N4   = Bc * Hc * Wc * C4;  // 2,097,152 pooled float4 groups
static constexpr int THREADS = 256;
static constexpr int BLOCKS  = N4 / THREADS;    // 8192 — exact, no tail

__global__ __launch_bounds__(THREADS) void max_unpool_final2(
    const float4* __restrict__ x4,
    const int4*   __restrict__ m4,
    float4*       __restrict__ out4)
{
    int idx = blockIdx.x * THREADS + threadIdx.x;   // always < N4 (exact grid)

    // Issue both loads immediately (read-once streaming).
    int4   m = __ldcs(&m4[idx]);
    float4 v = __ldcs(&x4[idx]);

    // idx -> (b, h, w, c4); all pow2 dims -> shifts/masks only.
    int c4 = idx & (C4 - 1);
    int t  = idx >> 4;
    int w  = t & (Wc - 1);
    t >>= 7;
    int h  = t & (Hc - 1);
    int b  = t >> 7;

    int c  = c4 << 2;
    int ho = h << 1;
    int wo = w << 1;

    // Output float4 offset of (b, ho, wo, c4).
    int obase = ((b * HOUT + ho) * WOUT + wo) * C4 + c4;
    // Expected argmax flat index (lane .x) at (ho, wo).
    int flat0 = (ho * WOUT + wo) * Cc + c;

#pragma unroll
    for (int dh = 0; dh < 2; ++dh) {
#pragma unroll
        for (int dw = 0; dw < 2; ++dw) {
            int flat = flat0 + dh * (WOUT * Cc) + dw * Cc;
            float4 o;
            o.x = (m.x == flat    ) ? v.x : 0.0f;
            o.y = (m.y == flat + 1) ? v.y : 0.0f;
            o.z = (m.z == flat + 2) ? v.z : 0.0f;
            o.w = (m.w == flat + 3) ? v.w : 0.0f;
            __stcg(&out4[obase + dh * (WOUT * C4) + dw * C4], o);
        }
    }
}

extern "C" void kernel_launch(void* const* d_in, const int* in_sizes, int n_in,
                              void* d_out, int out_size)
{
    const float4* x4 = (const float4*)d_in[0];   // input_pool float32
    const int4*   m4 = (const int4*)  d_in[1];   // pool_mask int32
    float4*       o4 = (float4*)d_out;

    max_unpool_final2<<<BLOCKS, THREADS>>>(x4, m4, o4);
}